// round 6
// baseline (speedup 1.0000x reference)
#include <cuda_runtime.h>

// Problem constants
#define S_LEN 2048
#define BATCH 4
#define HDIM  1024
#define MROWS (BATCH*S_LEN)        // 8192
#define SCALE_INV (0.03125f)       // 1/sqrt(1024) = 1/32

// Scratch (device globals: allocation-guard-safe)
__device__ float g_Q[(size_t)BATCH*S_LEN*HDIM];   // 32 MB, [B,S,H]
__device__ float g_K[(size_t)BATCH*S_LEN*HDIM];   // 32 MB
__device__ float g_V[(size_t)BATCH*S_LEN*HDIM];   // 32 MB
__device__ float g_P[(size_t)BATCH*S_LEN*S_LEN];  // 64 MB, [B,S,S]

typedef unsigned long long ull;

// ---- packed f32x2 helpers (B300: fma.rn.f32x2 doubles fp32 FMA throughput) ----
__device__ __forceinline__ ull pack_dup(float a) {
    ull r; asm("mov.b64 %0, {%1, %1};" : "=l"(r) : "f"(a)); return r;
}
__device__ __forceinline__ void fma2(ull &d, ull a, ull b) {
    asm("fma.rn.f32x2 %0, %1, %2, %0;" : "+l"(d) : "l"(a), "l"(b));
}
__device__ __forceinline__ float2 unpack2(ull v) {
    float2 f; asm("mov.b64 {%0, %1}, %2;" : "=f"(f.x), "=f"(f.y) : "l"(v)); return f;
}
union F4U { float4 f; ull u[2]; };

// ---- shared inner compute: 128x128 block tile, 8 k-steps ----
// Thread (tx,ty), tx=tid&15, ty=tid>>4. Fragment layout is the split 4+4:
//   rows:  {ty*4+0..3} U {64+ty*4+0..3}
//   cols:  {tx*4+0..3} U {64+tx*4+0..3}
// This keeps the Bs LDS.128 reads conflict-free (16 consecutive float4 per half).
__device__ __forceinline__ void mma_tile(const float (*As)[128], const float (*Bs)[128],
                                         int tx, int ty, ull acc[8][4])
{
#pragma unroll
    for (int kk = 0; kk < 8; kk++) {
        float4 a0 = *(const float4*)&As[kk][ty * 4];
        float4 a1 = *(const float4*)&As[kk][64 + ty * 4];
        F4U b0, b1;
        b0.f = *(const float4*)&Bs[kk][tx * 4];
        b1.f = *(const float4*)&Bs[kk][64 + tx * 4];
        ull bd[4] = { b0.u[0], b0.u[1], b1.u[0], b1.u[1] };
        float av[8] = { a0.x, a0.y, a0.z, a0.w, a1.x, a1.y, a1.z, a1.w };
#pragma unroll
        for (int i = 0; i < 8; i++) {
            ull ap = pack_dup(av[i]);
#pragma unroll
            for (int j = 0; j < 4; j++) fma2(acc[i][j], ap, bd[j]);
        }
    }
}

// =====================================================================
// Kernel 1: QKV projection.  out[b,s,o] = sum_h x[s,b,h]*W[o,h] + bias[o]
// A rows are indexed r = b*S + s (output order), so the result lands in
// [B,S,H] layout directly. which: 0->Q, 1->K, 2->V.
// Grid: (HDIM/128, MROWS/128) = (8, 64), 256 threads.
// =====================================================================
__global__ void __launch_bounds__(256, 2) proj_kernel(
    const float* __restrict__ x, const float* __restrict__ W,
    const float* __restrict__ bias, int which)
{
    __shared__ float As[8][128];
    __shared__ float Bs[8][128];
    const int tid = threadIdx.x;
    const int tx = tid & 15, ty = tid >> 4;
    const int m0 = blockIdx.y * 128;
    const int n0 = blockIdx.x * 128;

    // Tile loaders: 2 threads per row, each a float4 (32B sector per row).
    const int l_row = tid >> 1;         // 0..127
    const int l_k   = (tid & 1) * 4;    // 0 or 4
    const int r  = m0 + l_row;          // global row = b*S + s
    const int bb = r >> 11;             // / 2048
    const int ss = r & (S_LEN - 1);
    const float* aptr = x + (size_t)ss * (BATCH * HDIM) + (size_t)bb * HDIM + l_k;
    const float* bptr = W + (size_t)(n0 + l_row) * HDIM + l_k;

    ull acc[8][4];
#pragma unroll
    for (int i = 0; i < 8; i++)
#pragma unroll
        for (int j = 0; j < 4; j++) acc[i][j] = 0ull;

    for (int k0 = 0; k0 < HDIM; k0 += 8) {
        float4 av = *(const float4*)(aptr + k0);
        float4 bv = *(const float4*)(bptr + k0);
        As[l_k + 0][l_row] = av.x; As[l_k + 1][l_row] = av.y;
        As[l_k + 2][l_row] = av.z; As[l_k + 3][l_row] = av.w;
        Bs[l_k + 0][l_row] = bv.x; Bs[l_k + 1][l_row] = bv.y;
        Bs[l_k + 2][l_row] = bv.z; Bs[l_k + 3][l_row] = bv.w;
        __syncthreads();
        mma_tile(As, Bs, tx, ty, acc);
        __syncthreads();
    }

    float* out = (which == 0) ? g_Q : (which == 1) ? g_K : g_V;
#pragma unroll
    for (int hj = 0; hj < 2; hj++) {
        const int col = n0 + hj * 64 + tx * 4;
        float4 badd = *(const float4*)&bias[col];
#pragma unroll
        for (int hi = 0; hi < 2; hi++)
#pragma unroll
            for (int ii = 0; ii < 4; ii++) {
                const int i  = hi * 4 + ii;
                const int r2 = m0 + hi * 64 + ty * 4 + ii;
                float2 p0 = unpack2(acc[i][hj * 2]);
                float2 p1 = unpack2(acc[i][hj * 2 + 1]);
                float4 v = make_float4(p0.x + badd.x, p0.y + badd.y,
                                       p1.x + badd.z, p1.y + badd.w);
                *(float4*)&out[(size_t)r2 * HDIM + col] = v;
            }
    }
}

// =====================================================================
// Kernel 2: scores[b,q,k] = (Q[b,q,:].K[b,k,:]) / 32 + beta*ssm[b,q,k]
// Grid: (16, 16, 4)
// =====================================================================
__global__ void __launch_bounds__(256, 2) scores_kernel(
    const float* __restrict__ ssm, const float* __restrict__ beta_p)
{
    __shared__ float As[8][128];
    __shared__ float Bs[8][128];
    const int tid = threadIdx.x;
    const int tx = tid & 15, ty = tid >> 4;
    const int m0 = blockIdx.y * 128;
    const int n0 = blockIdx.x * 128;
    const int b  = blockIdx.z;

    const float* Qb = g_Q + (size_t)b * S_LEN * HDIM;
    const float* Kb = g_K + (size_t)b * S_LEN * HDIM;

    const int l_row = tid >> 1;
    const int l_k   = (tid & 1) * 4;
    const float* aptr = Qb + (size_t)(m0 + l_row) * HDIM + l_k;
    const float* bptr = Kb + (size_t)(n0 + l_row) * HDIM + l_k;

    ull acc[8][4];
#pragma unroll
    for (int i = 0; i < 8; i++)
#pragma unroll
        for (int j = 0; j < 4; j++) acc[i][j] = 0ull;

    for (int k0 = 0; k0 < HDIM; k0 += 8) {
        float4 av = *(const float4*)(aptr + k0);
        float4 bv = *(const float4*)(bptr + k0);
        As[l_k + 0][l_row] = av.x; As[l_k + 1][l_row] = av.y;
        As[l_k + 2][l_row] = av.z; As[l_k + 3][l_row] = av.w;
        Bs[l_k + 0][l_row] = bv.x; Bs[l_k + 1][l_row] = bv.y;
        Bs[l_k + 2][l_row] = bv.z; Bs[l_k + 3][l_row] = bv.w;
        __syncthreads();
        mma_tile(As, Bs, tx, ty, acc);
        __syncthreads();
    }

    const float beta = __ldg(beta_p);
    float*       Pb  = g_P + (size_t)b * S_LEN * S_LEN;
    const float* Sb  = ssm + (size_t)b * S_LEN * S_LEN;
#pragma unroll
    for (int hj = 0; hj < 2; hj++) {
        const int col = n0 + hj * 64 + tx * 4;
#pragma unroll
        for (int hi = 0; hi < 2; hi++)
#pragma unroll
            for (int ii = 0; ii < 4; ii++) {
                const int i  = hi * 4 + ii;
                const int r2 = m0 + hi * 64 + ty * 4 + ii;
                float2 p0 = unpack2(acc[i][hj * 2]);
                float2 p1 = unpack2(acc[i][hj * 2 + 1]);
                float4 sv = *(const float4*)&Sb[(size_t)r2 * S_LEN + col];
                float4 v = make_float4(p0.x * SCALE_INV + beta * sv.x,
                                       p0.y * SCALE_INV + beta * sv.y,
                                       p1.x * SCALE_INV + beta * sv.z,
                                       p1.y * SCALE_INV + beta * sv.w);
                *(float4*)&Pb[(size_t)r2 * S_LEN + col] = v;
            }
    }
}

// =====================================================================
// Kernel 3: row-wise stable softmax over g_P, 2048 elems/row, in place.
// One block (256 threads) per row, 8 elems per thread held in registers.
// =====================================================================
__global__ void __launch_bounds__(256) softmax_kernel()
{
    const int row = blockIdx.x;                 // 0..B*S-1
    float* p = g_P + (size_t)row * S_LEN;
    const int tid = threadIdx.x;

    float v[8];
    float mx = -1e30f;
#pragma unroll
    for (int i = 0; i < 8; i++) { v[i] = p[tid + (i << 8)]; mx = fmaxf(mx, v[i]); }

#pragma unroll
    for (int o = 16; o; o >>= 1) mx = fmaxf(mx, __shfl_xor_sync(0xffffffffu, mx, o));
    __shared__ float sred[8];
    if ((tid & 31) == 0) sred[tid >> 5] = mx;
    __syncthreads();
#pragma unroll
    for (int i = 0; i < 8; i++) mx = fmaxf(mx, sred[i]);

    float sum = 0.f;
#pragma unroll
    for (int i = 0; i < 8; i++) { v[i] = __expf(v[i] - mx); sum += v[i]; }
#pragma unroll
    for (int o = 16; o; o >>= 1) sum += __shfl_xor_sync(0xffffffffu, sum, o);
    __syncthreads();                            // protect sred reuse
    if ((tid & 31) == 0) sred[tid >> 5] = sum;
    __syncthreads();
    sum = 0.f;
#pragma unroll
    for (int i = 0; i < 8; i++) sum += sred[i];

    const float inv = 1.0f / sum;
#pragma unroll
    for (int i = 0; i < 8; i++) p[tid + (i << 8)] = v[i] * inv;
}

// =====================================================================
// Kernel 4: out[s,b,h] = sum_k attn[b,s,k] * V[b,k,h]
// A = P[b] (K-contiguous, K=2048); B = V[b] (N-contiguous, no transpose).
// Grid: (HDIM/128, S_LEN/128, BATCH) = (8, 16, 4)
// =====================================================================
__global__ void __launch_bounds__(256, 2) out_kernel(float* __restrict__ out)
{
    __shared__ float As[8][128];
    __shared__ float Bs[8][128];
    const int tid = threadIdx.x;
    const int tx = tid & 15, ty = tid >> 4;
    const int m0 = blockIdx.y * 128;
    const int n0 = blockIdx.x * 128;
    const int b  = blockIdx.z;

    const float* Pb = g_P + (size_t)b * S_LEN * S_LEN;
    const float* Vb = g_V + (size_t)b * S_LEN * HDIM;

    const int l_row = tid >> 1;
    const int l_k   = (tid & 1) * 4;
    const float* aptr = Pb + (size_t)(m0 + l_row) * S_LEN + l_k;

    // V tile loader: 8 k-rows x 128 n-cols, coalesced along n (no transpose).
    const int v_kk = tid >> 5;          // 0..7
    const int v_c  = (tid & 31) * 4;    // 0..124
    const float* vptr = Vb + (size_t)v_kk * HDIM + n0 + v_c;

    ull acc[8][4];
#pragma unroll
    for (int i = 0; i < 8; i++)
#pragma unroll
        for (int j = 0; j < 4; j++) acc[i][j] = 0ull;

    for (int k0 = 0; k0 < S_LEN; k0 += 8) {
        float4 av = *(const float4*)(aptr + k0);
        float4 bv = *(const float4*)(vptr + (size_t)k0 * HDIM);
        As[l_k + 0][l_row] = av.x; As[l_k + 1][l_row] = av.y;
        As[l_k + 2][l_row] = av.z; As[l_k + 3][l_row] = av.w;
        *(float4*)&Bs[v_kk][v_c] = bv;
        __syncthreads();
        mma_tile(As, Bs, tx, ty, acc);
        __syncthreads();
    }

#pragma unroll
    for (int hj = 0; hj < 2; hj++) {
        const int col = n0 + hj * 64 + tx * 4;        // h
#pragma unroll
        for (int hi = 0; hi < 2; hi++)
#pragma unroll
            for (int ii = 0; ii < 4; ii++) {
                const int i  = hi * 4 + ii;
                const int r2 = m0 + hi * 64 + ty * 4 + ii;   // s (query)
                float2 p0 = unpack2(acc[i][hj * 2]);
                float2 p1 = unpack2(acc[i][hj * 2 + 1]);
                float4 v = make_float4(p0.x, p0.y, p1.x, p1.y);
                // final layout [S,B,H]: idx = s*(B*H) + b*H + h
                *(float4*)&out[(size_t)r2 * (BATCH * HDIM) + (size_t)b * HDIM + col] = v;
            }
    }
}

// =====================================================================
extern "C" void kernel_launch(void* const* d_in, const int* in_sizes, int n_in,
                              void* d_out, int out_size)
{
    const float* x    = (const float*)d_in[0];
    const float* ssm  = (const float*)d_in[1];
    const float* Wq   = (const float*)d_in[2];
    const float* bq   = (const float*)d_in[3];
    const float* Wk   = (const float*)d_in[4];
    const float* bk   = (const float*)d_in[5];
    const float* Wv   = (const float*)d_in[6];
    const float* bv   = (const float*)d_in[7];
    const float* beta = (const float*)d_in[8];
    float* out = (float*)d_out;

    dim3 blk(256);
    dim3 gproj(HDIM / 128, MROWS / 128);          // (8, 64)
    proj_kernel<<<gproj, blk>>>(x, Wq, bq, 0);
    proj_kernel<<<gproj, blk>>>(x, Wk, bk, 1);
    proj_kernel<<<gproj, blk>>>(x, Wv, bv, 2);

    dim3 gsc(S_LEN / 128, S_LEN / 128, BATCH);    // (16, 16, 4)
    scores_kernel<<<gsc, blk>>>(ssm, beta);

    softmax_kernel<<<BATCH * S_LEN, 256>>>();     // 8192 rows

    dim3 gout(HDIM / 128, S_LEN / 128, BATCH);    // (8, 16, 4)
    out_kernel<<<gout, blk>>>(out);
}

// round 11
// speedup vs baseline: 1.7870x; 1.7870x over previous
#include <cuda_runtime.h>
#include <cstdint>

// ---------------- problem constants ----------------
#define S_LEN 2048
#define BATCH 4
#define HDIM  1024
#define MROWS (BATCH*S_LEN)        // 8192
#define SCALE_INV 0.03125f         // 1/sqrt(1024)

// ---------------- scratch (device globals; allocation-guard-safe) ----------
__device__ float g_Q [(size_t)BATCH*S_LEN*HDIM];   // [B,S,H]
__device__ float g_K [(size_t)BATCH*S_LEN*HDIM];   // [B,S,H]
__device__ float g_V [(size_t)BATCH*S_LEN*HDIM];   // [B,S,H]
__device__ float g_Vt[(size_t)BATCH*HDIM*S_LEN];   // [B,H,S]
__device__ float g_P [(size_t)BATCH*S_LEN*S_LEN];  // [B,S,S]

// ---------------- smem layout ----------------
// Row stride 40 bf16 = 80 B (32 data + 8 pad) -> fragment lds and split-stores
// hit 32 distinct banks (20*row + tig distinct mod 32 for row 0..7).
// Per stage: A_hi | A_lo | B_hi | B_lo, each 128 rows * 80 B = 10240 B.
#define ROWB   80
#define OFF_AH 0
#define OFF_AL 10240
#define OFF_BH 20480
#define OFF_BL 30720
#define STAGE  40960
#define SMEM_BYTES (2*STAGE)       // 81920

// ---------------- helpers ----------------
__device__ __forceinline__ uint32_t smem_u32(const void* p) {
    uint32_t a;
    asm("{ .reg .u64 t; cvta.to.shared.u64 t, %1; cvt.u32.u64 %0, t; }" : "=r"(a) : "l"(p));
    return a;
}
__device__ __forceinline__ uint32_t lds32(uint32_t a) {
    uint32_t v; asm volatile("ld.shared.b32 %0, [%1];" : "=r"(v) : "r"(a)); return v;
}
#define STS128(r0, r1, r2, r3, addr) \
    asm volatile("st.shared.v4.b32 [%0], {%1, %2, %3, %4};" \
        :: "r"(addr), "r"(r0), "r"(r1), "r"(r2), "r"(r3) : "memory")

// Split x into bf16 hi + bf16 lo (hi = rn(x), lo = rn(x - hi)).
// Packs two consecutive-k elements into one b32 (x0 -> low half).
__device__ __forceinline__ void split2(float x0, float x1, uint32_t& hi, uint32_t& lo) {
    uint32_t h;
    asm("cvt.rn.bf16x2.f32 %0, %1, %2;" : "=r"(h) : "f"(x1), "f"(x0));
    float h0 = __uint_as_float(h << 16);
    float h1 = __uint_as_float(h & 0xffff0000u);
    float l0 = x0 - h0, l1 = x1 - h1;
    asm("cvt.rn.bf16x2.f32 %0, %1, %2;" : "=r"(lo) : "f"(l1), "f"(l0));
    hi = h;
}

// m16n8k16 row.col bf16 -> f32 accumulate (Ampere-compatible, no 'a'-arch PTX)
#define MMA_BF16(d, a, b) \
    asm volatile("mma.sync.aligned.m16n8k16.row.col.f32.bf16.bf16.f32 " \
        "{%0,%1,%2,%3}, {%4,%5,%6,%7}, {%8,%9}, {%0,%1,%2,%3};" \
        : "+f"((d)[0]), "+f"((d)[1]), "+f"((d)[2]), "+f"((d)[3]) \
        : "r"((a)[0]), "r"((a)[1]), "r"((a)[2]), "r"((a)[3]), \
          "r"((b)[0]), "r"((b)[1]))

// Split one tile-row chunk (16 floats) of A and B and store hi/lo planes.
__device__ __forceinline__ void store_split(uint32_t stA, uint32_t stB,
                                            const float4* ra, const float4* rb)
{
    uint32_t h[8], l[8];
#pragma unroll
    for (int j = 0; j < 4; j++) {
        split2(ra[j].x, ra[j].y, h[2*j],   l[2*j]);
        split2(ra[j].z, ra[j].w, h[2*j+1], l[2*j+1]);
    }
    STS128(h[0], h[1], h[2], h[3], stA);
    STS128(h[4], h[5], h[6], h[7], stA + 16);
    STS128(l[0], l[1], l[2], l[3], stA + (OFF_AL - OFF_AH));
    STS128(l[4], l[5], l[6], l[7], stA + (OFF_AL - OFF_AH) + 16);
#pragma unroll
    for (int j = 0; j < 4; j++) {
        split2(rb[j].x, rb[j].y, h[2*j],   l[2*j]);
        split2(rb[j].z, rb[j].w, h[2*j+1], l[2*j+1]);
    }
    STS128(h[0], h[1], h[2], h[3], stB);
    STS128(h[4], h[5], h[6], h[7], stB + 16);
    STS128(l[0], l[1], l[2], l[3], stB + (OFF_BL - OFF_BH));
    STS128(l[4], l[5], l[6], l[7], stB + (OFF_BL - OFF_BH) + 16);
}

// ---------------- generic 128x128 GEMM mainloop (3xBF16 emulated fp32) ------
// acc[mt][nt][r] += sum_k A[m][k] * B[n][k]; warp layout 2(M) x 4(N),
// warp tile 64x32, double-buffered 128x128x32 smem stages.
__device__ __forceinline__ void gemm_main(const float* __restrict__ A, int lda,
                                          const float* __restrict__ B, int ldb,
                                          int K, char* smem, float acc[4][4][4])
{
    const int tid  = threadIdx.x;
    const int wid  = tid >> 5, lane = tid & 31;
    const int wm   = (wid >> 2) * 64;         // warp M offset (0/64)
    const int wn   = (wid & 3) * 32;          // warp N offset (0/32/64/96)
    const int g    = lane >> 2, tig = lane & 3;
    const uint32_t sb = smem_u32(smem);

    // loader: 2 threads per row, 16 floats each
    const int lrow = tid >> 1;
    const int k0   = (tid & 1) * 16;
    const float* aP = A + (size_t)lrow * lda + k0;
    const float* bP = B + (size_t)lrow * ldb + k0;
    const uint32_t stA = sb + OFF_AH + lrow * ROWB + (tid & 1) * 32;
    const uint32_t stB = sb + OFF_BH + lrow * ROWB + (tid & 1) * 32;

    // fragment read bases
    const uint32_t rdA = sb + OFF_AH + (wm + g) * ROWB + tig * 4;
    const uint32_t rdB = sb + OFF_BH + (wn + g) * ROWB + tig * 4;

    float4 ra[4], rb[4];
#pragma unroll
    for (int j = 0; j < 4; j++) {
        ra[j] = *(const float4*)(aP + j * 4);
        rb[j] = *(const float4*)(bP + j * 4);
    }
    store_split(stA, stB, ra, rb);
    __syncthreads();

    const int T = K >> 5;                     // 32-wide K tiles
    for (int t = 0; t < T; ++t) {
        const uint32_t so = (uint32_t)(t & 1) * STAGE;

        if (t + 1 < T) {                      // prefetch next tile into regs
            const int kk = (t + 1) << 5;
#pragma unroll
            for (int j = 0; j < 4; j++) {
                ra[j] = *(const float4*)(aP + kk + j * 4);
                rb[j] = *(const float4*)(bP + kk + j * 4);
            }
        }

#pragma unroll
        for (int ks = 0; ks < 2; ks++) {      // two k16 steps per tile
            const uint32_t co = so + ks * 32; // 16 bf16 = 32 B
            uint32_t ah[4][4], al[4][4], bh[4][2], bl[4][2];
#pragma unroll
            for (int mt = 0; mt < 4; mt++) {
                uint32_t ba = rdA + co + mt * (16 * ROWB);
                ah[mt][0] = lds32(ba);
                ah[mt][1] = lds32(ba + 8 * ROWB);
                ah[mt][2] = lds32(ba + 16);
                ah[mt][3] = lds32(ba + 8 * ROWB + 16);
                ba += (OFF_AL - OFF_AH);
                al[mt][0] = lds32(ba);
                al[mt][1] = lds32(ba + 8 * ROWB);
                al[mt][2] = lds32(ba + 16);
                al[mt][3] = lds32(ba + 8 * ROWB + 16);
            }
#pragma unroll
            for (int nt = 0; nt < 4; nt++) {
                uint32_t bb = rdB + co + nt * (8 * ROWB);
                bh[nt][0] = lds32(bb);
                bh[nt][1] = lds32(bb + 16);
                bb += (OFF_BL - OFF_BH);
                bl[nt][0] = lds32(bb);
                bl[nt][1] = lds32(bb + 16);
            }
#pragma unroll
            for (int mt = 0; mt < 4; mt++)
#pragma unroll
                for (int nt = 0; nt < 4; nt++) {
                    MMA_BF16(acc[mt][nt], ah[mt], bh[nt]);  // hi*hi
                    MMA_BF16(acc[mt][nt], ah[mt], bl[nt]);  // hi*lo
                    MMA_BF16(acc[mt][nt], al[mt], bh[nt]);  // lo*hi
                }
        }

        if (t + 1 < T)
            store_split(stA + ((uint32_t)((t + 1) & 1) * STAGE),
                        stB + ((uint32_t)((t + 1) & 1) * STAGE), ra, rb);
        __syncthreads();
    }
}

// Per-thread output coordinates for acc[mt][nt]:
//   row = m0 + wm + mt*16 + g  (and row+8 for regs 2,3)
//   col = n0 + wn + nt*8 + tig*2  (regs {0,1} and {2,3} are col, col+1)

// =====================================================================
// Kernel 1: QKV projection. out[r,o] = sum_h x[s,b,h]*W[o,h] + b[o]
// r = b*S + s -> result lands in [B,S,H]. grid (8, 64), 256 thr.
// =====================================================================
__global__ void __launch_bounds__(256, 1) proj_mma(
    const float* __restrict__ x, const float* __restrict__ W,
    const float* __restrict__ bias, int which)
{
    extern __shared__ char smem[];
    const int m0 = blockIdx.y * 128;
    const int n0 = blockIdx.x * 128;
    const int bb = m0 >> 11;
    const int s0 = m0 & (S_LEN - 1);
    const float* Abase = x + ((size_t)s0 * BATCH + bb) * HDIM;  // row stride B*H
    const float* Bbase = W + (size_t)n0 * HDIM;

    float acc[4][4][4];
#pragma unroll
    for (int i = 0; i < 4; i++)
#pragma unroll
        for (int j = 0; j < 4; j++)
#pragma unroll
            for (int r = 0; r < 4; r++) acc[i][j][r] = 0.f;

    gemm_main(Abase, BATCH * HDIM, Bbase, HDIM, HDIM, smem, acc);

    float* outp = (which == 0) ? g_Q : (which == 1) ? g_K : g_V;
    const int tid = threadIdx.x, wid = tid >> 5, lane = tid & 31;
    const int wm = (wid >> 2) * 64, wn = (wid & 3) * 32;
    const int g = lane >> 2, tig = lane & 3;
#pragma unroll
    for (int mt = 0; mt < 4; mt++)
#pragma unroll
        for (int nt = 0; nt < 4; nt++) {
            const int row = m0 + wm + mt * 16 + g;
            const int col = n0 + wn + nt * 8 + tig * 2;
            const float2 bv = *(const float2*)(bias + col);
            float2 o0 = make_float2(acc[mt][nt][0] + bv.x, acc[mt][nt][1] + bv.y);
            float2 o1 = make_float2(acc[mt][nt][2] + bv.x, acc[mt][nt][3] + bv.y);
            *(float2*)(outp + (size_t)row * HDIM + col)       = o0;
            *(float2*)(outp + (size_t)(row + 8) * HDIM + col) = o1;
        }
}

// =====================================================================
// Kernel 2: V transpose  g_Vt[b][h][s] = g_V[b][s][h]
// =====================================================================
__global__ void __launch_bounds__(256) transpose_v()
{
    __shared__ float tile[32][33];
    const int b  = blockIdx.z;
    const int s0 = blockIdx.x * 32;
    const int h0 = blockIdx.y * 32;
    const int tx = threadIdx.x, ty = threadIdx.y;
    const float* src = g_V + ((size_t)b * S_LEN + s0) * HDIM + h0;
#pragma unroll
    for (int i = 0; i < 32; i += 8)
        tile[ty + i][tx] = src[(size_t)(ty + i) * HDIM + tx];
    __syncthreads();
    float* dst = g_Vt + ((size_t)b * HDIM + h0) * S_LEN + s0;
#pragma unroll
    for (int i = 0; i < 32; i += 8)
        dst[(size_t)(ty + i) * S_LEN + tx] = tile[tx][ty + i];
}

// =====================================================================
// Kernel 3: scores  P[b,q,k] = (Q[b,q,:].K[b,k,:])/32 + beta*ssm[b,q,k]
// grid (16, 16, 4)
// =====================================================================
__global__ void __launch_bounds__(256, 1) scores_mma(
    const float* __restrict__ ssm, const float* __restrict__ beta_p)
{
    extern __shared__ char smem[];
    const int q0 = blockIdx.y * 128;
    const int kk0 = blockIdx.x * 128;
    const int b  = blockIdx.z;
    const float* Abase = g_Q + (size_t)b * S_LEN * HDIM + (size_t)q0 * HDIM;
    const float* Bbase = g_K + (size_t)b * S_LEN * HDIM + (size_t)kk0 * HDIM;

    float acc[4][4][4];
#pragma unroll
    for (int i = 0; i < 4; i++)
#pragma unroll
        for (int j = 0; j < 4; j++)
#pragma unroll
            for (int r = 0; r < 4; r++) acc[i][j][r] = 0.f;

    gemm_main(Abase, HDIM, Bbase, HDIM, HDIM, smem, acc);

    const float beta = __ldg(beta_p);
    const int tid = threadIdx.x, wid = tid >> 5, lane = tid & 31;
    const int wm = (wid >> 2) * 64, wn = (wid & 3) * 32;
    const int g = lane >> 2, tig = lane & 3;
    float*       Pb = g_P + (size_t)b * S_LEN * S_LEN;
    const float* Sb = ssm + (size_t)b * S_LEN * S_LEN;
#pragma unroll
    for (int mt = 0; mt < 4; mt++)
#pragma unroll
        for (int nt = 0; nt < 4; nt++) {
            const int row = q0 + wm + mt * 16 + g;
            const int col = kk0 + wn + nt * 8 + tig * 2;
            const float2 s0 = *(const float2*)(Sb + (size_t)row * S_LEN + col);
            const float2 s1 = *(const float2*)(Sb + (size_t)(row + 8) * S_LEN + col);
            float2 o0 = make_float2(acc[mt][nt][0] * SCALE_INV + beta * s0.x,
                                    acc[mt][nt][1] * SCALE_INV + beta * s0.y);
            float2 o1 = make_float2(acc[mt][nt][2] * SCALE_INV + beta * s1.x,
                                    acc[mt][nt][3] * SCALE_INV + beta * s1.y);
            *(float2*)(Pb + (size_t)row * S_LEN + col)       = o0;
            *(float2*)(Pb + (size_t)(row + 8) * S_LEN + col) = o1;
        }
}

// =====================================================================
// Kernel 4: row-wise stable softmax over g_P, in place (unchanged, proven)
// =====================================================================
__global__ void __launch_bounds__(256) softmax_kernel()
{
    const int row = blockIdx.x;
    float* p = g_P + (size_t)row * S_LEN;
    const int tid = threadIdx.x;

    float v[8];
    float mx = -1e30f;
#pragma unroll
    for (int i = 0; i < 8; i++) { v[i] = p[tid + (i << 8)]; mx = fmaxf(mx, v[i]); }
#pragma unroll
    for (int o = 16; o; o >>= 1) mx = fmaxf(mx, __shfl_xor_sync(0xffffffffu, mx, o));
    __shared__ float sred[8];
    if ((tid & 31) == 0) sred[tid >> 5] = mx;
    __syncthreads();
#pragma unroll
    for (int i = 0; i < 8; i++) mx = fmaxf(mx, sred[i]);

    float sum = 0.f;
#pragma unroll
    for (int i = 0; i < 8; i++) { v[i] = __expf(v[i] - mx); sum += v[i]; }
#pragma unroll
    for (int o = 16; o; o >>= 1) sum += __shfl_xor_sync(0xffffffffu, sum, o);
    __syncthreads();
    if ((tid & 31) == 0) sred[tid >> 5] = sum;
    __syncthreads();
    sum = 0.f;
#pragma unroll
    for (int i = 0; i < 8; i++) sum += sred[i];

    const float inv = 1.0f / sum;
#pragma unroll
    for (int i = 0; i < 8; i++) p[tid + (i << 8)] = v[i] * inv;
}

// =====================================================================
// Kernel 5: out[s,b,h] = sum_k P[b,s,k] * Vt[b,h,k]
// grid (8, 16, 4)
// =====================================================================
__global__ void __launch_bounds__(256, 1) out_mma(float* __restrict__ out)
{
    extern __shared__ char smem[];
    const int q0 = blockIdx.y * 128;
    const int h0 = blockIdx.x * 128;
    const int b  = blockIdx.z;
    const float* Abase = g_P  + (size_t)b * S_LEN * S_LEN + (size_t)q0 * S_LEN;
    const float* Bbase = g_Vt + (size_t)b * HDIM * S_LEN + (size_t)h0 * S_LEN;

    float acc[4][4][4];
#pragma unroll
    for (int i = 0; i < 4; i++)
#pragma unroll
        for (int j = 0; j < 4; j++)
#pragma unroll
            for (int r = 0; r < 4; r++) acc[i][j][r] = 0.f;

    gemm_main(Abase, S_LEN, Bbase, S_LEN, S_LEN, smem, acc);

    const int tid = threadIdx.x, wid = tid >> 5, lane = tid & 31;
    const int wm = (wid >> 2) * 64, wn = (wid & 3) * 32;
    const int g = lane >> 2, tig = lane & 3;
#pragma unroll
    for (int mt = 0; mt < 4; mt++)
#pragma unroll
        for (int nt = 0; nt < 4; nt++) {
            const int row = q0 + wm + mt * 16 + g;         // s (query)
            const int col = h0 + wn + nt * 8 + tig * 2;    // h
            float* d0 = out + (size_t)row * (BATCH * HDIM) + (size_t)b * HDIM + col;
            float* d1 = out + (size_t)(row + 8) * (BATCH * HDIM) + (size_t)b * HDIM + col;
            *(float2*)d0 = make_float2(acc[mt][nt][0], acc[mt][nt][1]);
            *(float2*)d1 = make_float2(acc[mt][nt][2], acc[mt][nt][3]);
        }
}

// =====================================================================
extern "C" void kernel_launch(void* const* d_in, const int* in_sizes, int n_in,
                              void* d_out, int out_size)
{
    const float* x    = (const float*)d_in[0];
    const float* ssm  = (const float*)d_in[1];
    const float* Wq   = (const float*)d_in[2];
    const float* bq   = (const float*)d_in[3];
    const float* Wk   = (const float*)d_in[4];
    const float* bk   = (const float*)d_in[5];
    const float* Wv   = (const float*)d_in[6];
    const float* bv   = (const float*)d_in[7];
    const float* beta = (const float*)d_in[8];
    float* out = (float*)d_out;

    cudaFuncSetAttribute(proj_mma,   cudaFuncAttributeMaxDynamicSharedMemorySize, SMEM_BYTES);
    cudaFuncSetAttribute(scores_mma, cudaFuncAttributeMaxDynamicSharedMemorySize, SMEM_BYTES);
    cudaFuncSetAttribute(out_mma,    cudaFuncAttributeMaxDynamicSharedMemorySize, SMEM_BYTES);

    dim3 blk(256);
    proj_mma<<<dim3(HDIM / 128, MROWS / 128), blk, SMEM_BYTES>>>(x, Wq, bq, 0);
    proj_mma<<<dim3(HDIM / 128, MROWS / 128), blk, SMEM_BYTES>>>(x, Wk, bk, 1);
    proj_mma<<<dim3(HDIM / 128, MROWS / 128), blk, SMEM_BYTES>>>(x, Wv, bv, 2);

    transpose_v<<<dim3(S_LEN / 32, HDIM / 32, BATCH), dim3(32, 8)>>>();

    scores_mma<<<dim3(S_LEN / 128, S_LEN / 128, BATCH), blk, SMEM_BYTES>>>(ssm, beta);

    softmax_kernel<<<BATCH * S_LEN, 256>>>();

    out_mma<<<dim3(HDIM / 128, S_LEN / 128, BATCH), blk, SMEM_BYTES>>>(out);
}